// round 7
// baseline (speedup 1.0000x reference)
#include <cuda_runtime.h>
#include <cstdint>

// FP8 E4M3 bit-plane multiply -> exact FP32 bit-plane.
// v2: 2 elements per thread (64 per warp) for MLP=8 front-batched loads,
// shuffle-coalesced float4 stores with streaming (__stcs) hint.

__device__ __forceinline__ uint32_t pack_byte(uint4 lo, uint4 hi) {
    // lo = {s, e3, e2, e1}, hi = {e0, m2, m1, m0}; result bit7=s .. bit0=m0.
    // bit-plane float is 0x3F800000 (1.0f) or 0x0, so bit23 carries the value.
    uint32_t v;
    v  = (lo.x >> 16) & 0x80u;  // s  -> bit 7
    v |= (lo.y >> 17) & 0x40u;  // e3 -> bit 6
    v |= (lo.z >> 18) & 0x20u;  // e2 -> bit 5
    v |= (lo.w >> 19) & 0x10u;  // e1 -> bit 4
    v |= (hi.x >> 20) & 0x08u;  // e0 -> bit 3
    v |= (hi.y >> 21) & 0x04u;  // m2 -> bit 2
    v |= (hi.z >> 22) & 0x02u;  // m1 -> bit 1
    v |= (hi.w >> 23) & 0x01u;  // m0 -> bit 0
    return v;
}

// Exact FP8(E4M3) x FP8 -> FP32 bit pattern from two packed FP8 bytes.
__device__ __forceinline__ uint32_t fp8_mul_word(uint32_t va, uint32_t vb) {
    // decode A
    uint32_t ma = va & 7u, ea4 = (va >> 3) & 15u;
    int pa = 31 - __clz(ma | 1u);
    uint32_t fa = ea4 ? (ma + 8u) : (ma << (3 - pa));
    int      ea = ea4 ? (int)ea4 + 120 : 118 + pa;
    // decode B
    uint32_t mb = vb & 7u, eb4 = (vb >> 3) & 15u;
    int pb = 31 - __clz(mb | 1u);
    uint32_t fb = eb4 ? (mb + 8u) : (mb << (3 - pb));
    int      eb = eb4 ? (int)eb4 + 120 : 118 + pb;

    const uint32_t p     = fa * fb;               // [64,225] when both nonzero
    const uint32_t carry = p >> 7;
    const uint32_t pn    = p << (1u - carry);     // leading one -> bit 7
    const int      eo    = ea + eb - 127 + (int)carry;

    uint32_t body = ((uint32_t)eo << 23) | ((pn & 0x7Fu) << 16);
    const bool nz = ((va & 0x7Fu) != 0u) & ((vb & 0x7Fu) != 0u);
    return (((va ^ vb) & 0x80u) << 24) | (nz ? body : 0u);
}

__global__ void __launch_bounds__(256)
spike_fp8_mul_kernel(const uint4* __restrict__ A4,
                     const uint4* __restrict__ B4,
                     float4* __restrict__ O4,
                     int n_elem) {
    const int tid  = blockIdx.x * blockDim.x + threadIdx.x;
    const int lane = threadIdx.x & 31;
    const int eb   = (tid - lane) * 2;       // warp's base element (64 per warp)
    const int e0   = eb + lane;
    const int e1   = eb + 32 + lane;

    uint32_t w0 = 0u, w1 = 0u;
    if (e1 < n_elem) {
        // Front-batch all 8 loads (MLP=8) before any dependent compute.
        const uint4 a0l = A4[(size_t)e0 * 2 + 0];
        const uint4 a0h = A4[(size_t)e0 * 2 + 1];
        const uint4 b0l = B4[(size_t)e0 * 2 + 0];
        const uint4 b0h = B4[(size_t)e0 * 2 + 1];
        const uint4 a1l = A4[(size_t)e1 * 2 + 0];
        const uint4 a1h = A4[(size_t)e1 * 2 + 1];
        const uint4 b1l = B4[(size_t)e1 * 2 + 0];
        const uint4 b1h = B4[(size_t)e1 * 2 + 1];

        w0 = fp8_mul_word(pack_byte(a0l, a0h), pack_byte(b0l, b0h));
        w1 = fp8_mul_word(pack_byte(a1l, a1h), pack_byte(b1l, b1h));
    } else if (e0 < n_elem) {
        const uint4 a0l = A4[(size_t)e0 * 2 + 0];
        const uint4 a0h = A4[(size_t)e0 * 2 + 1];
        const uint4 b0l = B4[(size_t)e0 * 2 + 0];
        const uint4 b0h = B4[(size_t)e0 * 2 + 1];
        w0 = fp8_mul_word(pack_byte(a0l, a0h), pack_byte(b0l, b0h));
    }

    // Warp-coalesced output: iteration k writes float4 index eb*8 + k*32 + lane,
    // i.e. 512B contiguous per warp per iteration. That float4 belongs to
    // element eb + k*4 + (lane>>3), bit group [4*(lane&7), +4).
    const uint32_t j0 = (uint32_t)(lane & 7) * 4u;
    const int      sl = lane >> 3;
#pragma unroll
    for (int k = 0; k < 16; ++k) {
        const uint32_t w = (k < 8)
            ? __shfl_sync(0xFFFFFFFFu, w0, k * 4 + sl)
            : __shfl_sync(0xFFFFFFFFu, w1, (k - 8) * 4 + sl);
        const uint32_t ws = w << j0;     // target bit group now at bits 31..28
        float4 f;
        f.x = __uint_as_float(((int)(ws      ) >> 31) & 0x3F800000);
        f.y = __uint_as_float(((int)(ws << 1) >> 31) & 0x3F800000);
        f.z = __uint_as_float(((int)(ws << 2) >> 31) & 0x3F800000);
        f.w = __uint_as_float(((int)(ws << 3) >> 31) & 0x3F800000);
        const int src_elem = eb + k * 4 + sl;
        if (src_elem < n_elem)
            __stcs(&O4[(size_t)eb * 8 + (size_t)k * 32 + lane], f);
    }
}

extern "C" void kernel_launch(void* const* d_in, const int* in_sizes, int n_in,
                              void* d_out, int out_size) {
    const uint4* A4 = (const uint4*)d_in[0];
    const uint4* B4 = (const uint4*)d_in[1];
    float4* O4 = (float4*)d_out;

    const int n_elem  = in_sizes[0] / 8;      // 1024*4096 = 4,194,304
    const int threads = 256;
    const int elems_per_block = threads * 2;
    const int blocks  = (n_elem + elems_per_block - 1) / elems_per_block;

    spike_fp8_mul_kernel<<<blocks, threads>>>(A4, B4, O4, n_elem);
}